// round 9
// baseline (speedup 1.0000x reference)
#include <cuda_runtime.h>
#include <cuda_bf16.h>
#include <cstdint>

// Problem constants
#define BB 128
#define DD 2048
#define NN 2048
#define TT 64
#define MM (BB * TT)   // 8192 rows of the GEMM

// Hypothesized reference accumulation: block-K chunked fp32, kc = 64
// (Triton acc += tl.dot(...) BLOCK_K=64, or cuBLAS BF16x9-emulated SGEMM
// with 64-wide tensor-core K-chunks and fp32 chunk adds).
// psp = ((chunk0 + chunk1) + chunk2) + ... , plain fp32 add per boundary,
// ascending-k FMA chain within each 64-wide chunk. 32 chunks total.
#define KCHUNK 64

// Scratch (allocations are forbidden; __device__ globals are the sanctioned path)
__device__ float g_X[(size_t)MM * DD];    // transposed input: [B*T, D]
__device__ float g_psp[(size_t)MM * NN];  // GEMM output:      [B*T, N]

// ---------------------------------------------------------------------------
// Kernel 1: transpose input_spikes [B, D, T] -> X [B*T, D]
// ---------------------------------------------------------------------------
__global__ __launch_bounds__(256) void k_transpose(const float* __restrict__ in) {
    __shared__ float tile[32][33];
    const int b  = blockIdx.z;
    const int d0 = blockIdx.y * 32;
    const int t0 = blockIdx.x * 32;
    const int tx = threadIdx.x;        // 0..31
    const int ty = threadIdx.y;        // 0..7

#pragma unroll
    for (int i = ty; i < 32; i += 8) {
        tile[i][tx] = in[((size_t)b * DD + (d0 + i)) * TT + (t0 + tx)];
    }
    __syncthreads();
#pragma unroll
    for (int i = ty; i < 32; i += 8) {
        g_X[((size_t)b * TT + (t0 + i)) * DD + (d0 + tx)] = tile[tx][i];
    }
}

// ---------------------------------------------------------------------------
// Kernel 2: fp32 GEMM with block-K chunked accumulation (kc = 64)
//   psp[m,n] = (((c0 + c1) + c2) + ... + c31) + bias[n]
//   c_i = ascending-k FMA chain over k in [i*64, (i+1)*64)
//
// This is a BIT-EXACTNESS replication attempt of the reference's summation
// order, not an accuracy improvement. Do not reorder.
//
// Tiling: CTA 128(m) x 64(n), TK=16, 256 threads, 8x4 micro-tile.
// ---------------------------------------------------------------------------
#define TM 128
#define TN 64
#define TK 16

__global__ __launch_bounds__(256) void k_gemm(const float* __restrict__ W,
                                              const float* __restrict__ bias) {
    __shared__ float As[TK][TM];   // 8 KB
    __shared__ float Bs[TK][TN];   // 4 KB

    const int tid = threadIdx.x;
    const int m0  = blockIdx.y * TM;
    const int n0  = blockIdx.x * TN;

    // X load: 128 rows x 16 cols = 512 float4, 2 per thread
    const int xq0_row = (tid * 2) >> 2;
    const int xq0_c4  = ((tid * 2) & 3) * 4;
    const int xq1_row = (tid * 2 + 1) >> 2;
    const int xq1_c4  = ((tid * 2 + 1) & 3) * 4;
    // W load: 64 rows x 16 cols = 256 float4, 1 per thread
    const int wrow = tid >> 2;
    const int wc4  = (tid & 3) * 4;

    // compute mapping: 16x16 thread grid; thread owns 8 m x 4 n outputs
    const int tx = tid & 15;   // n block: tx*4
    const int ty = tid >> 4;   // m block: ty*8

    float acc[8][4], blk[8][4];
#pragma unroll
    for (int i = 0; i < 8; ++i)
#pragma unroll
        for (int j = 0; j < 4; ++j) { acc[i][j] = 0.0f; blk[i][j] = 0.0f; }

    for (int k0 = 0; k0 < DD; k0 += TK) {
        // ---- global -> smem ----
        {
            const float4 a0 = *(const float4*)&g_X[(size_t)(m0 + xq0_row) * DD + k0 + xq0_c4];
            const float4 a1 = *(const float4*)&g_X[(size_t)(m0 + xq1_row) * DD + k0 + xq1_c4];
            const float4 w  = *(const float4*)&W  [(size_t)(n0 + wrow)   * DD + k0 + wc4];
            As[xq0_c4 + 0][xq0_row] = a0.x;
            As[xq0_c4 + 1][xq0_row] = a0.y;
            As[xq0_c4 + 2][xq0_row] = a0.z;
            As[xq0_c4 + 3][xq0_row] = a0.w;
            As[xq1_c4 + 0][xq1_row] = a1.x;
            As[xq1_c4 + 1][xq1_row] = a1.y;
            As[xq1_c4 + 2][xq1_row] = a1.z;
            As[xq1_c4 + 3][xq1_row] = a1.w;
            Bs[wc4 + 0][wrow] = w.x;
            Bs[wc4 + 1][wrow] = w.y;
            Bs[wc4 + 2][wrow] = w.z;
            Bs[wc4 + 3][wrow] = w.w;
        }
        __syncthreads();

        // ---- ascending-k FMA chain within the current 64-wide chunk ----
#pragma unroll
        for (int k = 0; k < TK; ++k) {
            float ra[8], rb[4];
            const float4 a0 = *(const float4*)&As[k][ty * 8 + 0];
            const float4 a1 = *(const float4*)&As[k][ty * 8 + 4];
            const float4 b0 = *(const float4*)&Bs[k][tx * 4 + 0];
            ra[0] = a0.x; ra[1] = a0.y; ra[2] = a0.z; ra[3] = a0.w;
            ra[4] = a1.x; ra[5] = a1.y; ra[6] = a1.z; ra[7] = a1.w;
            rb[0] = b0.x; rb[1] = b0.y; rb[2] = b0.z; rb[3] = b0.w;
#pragma unroll
            for (int i = 0; i < 8; ++i)
#pragma unroll
                for (int j = 0; j < 4; ++j)
                    blk[i][j] = fmaf(ra[i], rb[j], blk[i][j]);
        }
        __syncthreads();

        // ---- chunk boundary every 64 k: plain fp32 add ----
        if (((k0 + TK) % KCHUNK) == 0) {
#pragma unroll
            for (int i = 0; i < 8; ++i)
#pragma unroll
                for (int j = 0; j < 4; ++j) {
                    acc[i][j] = __fadd_rn(acc[i][j], blk[i][j]);
                    blk[i][j] = 0.0f;
                }
        }
    }

    // 2048 % 64 == 0: all chunks already folded; blk is zero here.

    // epilogue: add bias (separately rounded), store
#pragma unroll
    for (int i = 0; i < 8; ++i) {
        const int m = m0 + ty * 8 + i;
        const int n = n0 + tx * 4;
        float4 o;
        o.x = __fadd_rn(acc[i][0], bias[n + 0]);
        o.y = __fadd_rn(acc[i][1], bias[n + 1]);
        o.z = __fadd_rn(acc[i][2], bias[n + 2]);
        o.w = __fadd_rn(acc[i][3], bias[n + 3]);
        *(float4*)&g_psp[(size_t)m * NN + n] = o;
    }
}

// ---------------------------------------------------------------------------
// Kernel 3: LIF hard-reset scan over T. Non-contracted fp32 update (matches
// XLA's op-by-op rounding; R1 vs R2 showed result is insensitive anyway).
// ---------------------------------------------------------------------------
__global__ __launch_bounds__(256) void k_scan(const float* __restrict__ decay,
                                              float* __restrict__ out,
                                              int write_vfinal) {
    const int idx = blockIdx.x * blockDim.x + threadIdx.x;  // b*N + n
    const int b = idx / NN;
    const int n = idx - b * NN;

    const float dec = decay[n];
    float v = 0.0f, s = 0.0f;
    float sp[TT];

    const float* p = g_psp + (size_t)b * TT * NN + n;
#pragma unroll
    for (int t = 0; t < TT; ++t) {
        float a = __fsub_rn(1.0f, s);
        float c = __fmul_rn(a, v);
        float d = __fmul_rn(c, dec);
        v = __fadd_rn(d, p[(size_t)t * NN]);
        s = (v > 0.5f) ? 1.0f : 0.0f;
        sp[t] = s;
    }

    float* o = out + (size_t)idx * TT;
#pragma unroll
    for (int t = 0; t < TT; t += 4) {
        *(float4*)&o[t] = make_float4(sp[t], sp[t + 1], sp[t + 2], sp[t + 3]);
    }
    if (write_vfinal) {
        out[(size_t)BB * NN * TT + idx] = v;
    }
}

// ---------------------------------------------------------------------------
extern "C" void kernel_launch(void* const* d_in, const int* in_sizes, int n_in,
                              void* d_out, int out_size) {
    const float* input = (const float*)d_in[0];  // [B, D, T]
    const float* W     = (const float*)d_in[1];  // [N, D]
    const float* bias  = (const float*)d_in[2];  // [N]
    const float* decay = (const float*)d_in[3];  // [N]
    float* out = (float*)d_out;

    const int write_vfinal =
        (out_size >= (int)((size_t)BB * NN * TT + (size_t)BB * NN)) ? 1 : 0;

    {
        dim3 grid(TT / 32, DD / 32, BB);
        dim3 block(32, 8);
        k_transpose<<<grid, block>>>(input);
    }
    {
        dim3 grid(NN / TN, MM / TM);   // 32 x 64
        k_gemm<<<grid, 256>>>(W, bias);
    }
    {
        const int total = BB * NN;
        k_scan<<<total / 256, 256>>>(decay, out, write_vfinal);
    }
}

// round 12
// speedup vs baseline: 2.0583x; 2.0583x over previous
#include <cuda_runtime.h>
#include <cuda_bf16.h>
#include <cstdint>

// Problem constants
#define BB 128
#define DD 2048
#define NN 2048
#define TT 64
#define MM (BB * TT)   // 8192 rows of the GEMM

// FROZEN NUMERICS (validated R9, rel_err 6.36e-4):
//   psp[m,n] = fold over 64-wide k-chunks (plain fp32 add per boundary),
//   ascending-k fp32 FMA chain within each chunk, bias added last, then
//   op-by-op rounded LIF scan. Any change to this per-output op order is a
//   correctness regression. f32x2 packed ops are bit-identical per lane.
#define KCHUNK 64

// Scratch
__device__ float g_psp[(size_t)MM * NN];  // GEMM output: [B*T, N]

// ---- packed fp32x2 helpers (Blackwell; lane-wise IEEE fp32 rn) ----
#define FMA2(d, a, b) \
    asm("fma.rn.f32x2 %0, %1, %2, %0;" : "+l"(d) : "l"(a), "l"(b))
#define ADD2(d, a, b) \
    asm("add.rn.f32x2 %0, %1, %2;" : "=l"(d) : "l"(a), "l"(b))
#define PACK2(d, lo, hi) \
    asm("mov.b64 %0, {%1, %2};" : "=l"(d) : "r"(__float_as_uint(lo)), "r"(__float_as_uint(hi)))
#define UNPACK2(lo, hi, s) \
    do { unsigned int _ulo, _uhi; \
         asm("mov.b64 {%0, %1}, %2;" : "=r"(_ulo), "=r"(_uhi) : "l"(s)); \
         lo = __uint_as_float(_ulo); hi = __uint_as_float(_uhi); } while (0)

// ---------------------------------------------------------------------------
// GEMM: psp[m,n] = chunked_sum_k X[m,k]*W[n,k] + bias[n]
//   X[m,k] = in[b, k, t] with m = b*64 + t  (loaded directly; no transpose)
// CTA tile 128(m) x 128(n), TK=16, 256 threads, 8x8 micro-tile with
// n-paired f32x2 accumulators. Double-buffered smem, 1 sync per tile.
// ---------------------------------------------------------------------------
#define TM 128
#define TN 128
#define TK 16
#define LDA (TM + 4)   // 132 floats = 528B, 16B-aligned rows
#define LDB (TN + 4)

typedef unsigned long long ull;

__global__ __launch_bounds__(256) void k_gemm(const float* __restrict__ in,
                                              const float* __restrict__ W,
                                              const float* __restrict__ bias) {
    __shared__ float As[2][TK][LDA];   // 16.5 KB
    __shared__ float Bs[2][TK][LDB];   // 16.5 KB

    const int tid = threadIdx.x;
    const int m0  = blockIdx.y * TM;
    const int n0  = blockIdx.x * TN;

    // ---- A loader: slots tid and tid+256 over 16k x 32 (m/4) grid ----
    // slot s: kk = s>>5 (slot1: kk+8), lm4 = (s&31)*4 (same for both)
    const int kkA  = tid >> 5;             // 0..7
    const int lm4  = (tid & 31) * 4;       // 0..124
    const int bA   = (m0 + lm4) >> 6;      // batch
    const int tA   = (m0 + lm4) & 63;      // time
    const float* aptr = in + ((size_t)bA * DD + kkA) * TT + tA;
    // per-tile advance: +TK*TT; kk+8 offset: +8*TT

    // ---- B loader: slots tid and tid+256 over 128(n) x 4 (k/4) grid ----
    const int lnB  = tid >> 2;             // 0..63 (slot1: +64)
    const int kc4  = (tid & 3) * 4;        // 0,4,8,12
    const float* wptr = W + (size_t)(n0 + lnB) * DD + kc4;
    // per-tile advance: +TK; ln+64 offset: +64*DD

    // ---- compute map: 16x16 threads, 8m x 8n (4 f32x2 pairs) ----
    const int tx = tid & 15;
    const int ty = tid >> 4;

    ull acc2[8][4], blk2[8][4];
    const ull zero2 = 0ull;
#pragma unroll
    for (int i = 0; i < 8; ++i)
#pragma unroll
        for (int j = 0; j < 4; ++j) { acc2[i][j] = zero2; blk2[i][j] = zero2; }

    // prologue: prefetch tile 0
    float4 pa0 = *(const float4*)(aptr);
    float4 pa1 = *(const float4*)(aptr + 8 * TT);
    float4 pw0 = *(const float4*)(wptr);
    float4 pw1 = *(const float4*)(wptr + (size_t)64 * DD);

    const int NTILES = DD / TK;  // 128
    int buf = 0;

    for (int tile = 0; tile < NTILES; ++tile) {
        // store prefetched tile to smem[buf]
        *(float4*)&As[buf][kkA][lm4]     = pa0;
        *(float4*)&As[buf][kkA + 8][lm4] = pa1;
        Bs[buf][kc4 + 0][lnB] = pw0.x;
        Bs[buf][kc4 + 1][lnB] = pw0.y;
        Bs[buf][kc4 + 2][lnB] = pw0.z;
        Bs[buf][kc4 + 3][lnB] = pw0.w;
        Bs[buf][kc4 + 0][lnB + 64] = pw1.x;
        Bs[buf][kc4 + 1][lnB + 64] = pw1.y;
        Bs[buf][kc4 + 2][lnB + 64] = pw1.z;
        Bs[buf][kc4 + 3][lnB + 64] = pw1.w;
        __syncthreads();

        // prefetch next tile into registers
        if (tile + 1 < NTILES) {
            const float* ap = aptr + (size_t)(tile + 1) * TK * TT;
            const float* wp = wptr + (size_t)(tile + 1) * TK;
            pa0 = *(const float4*)(ap);
            pa1 = *(const float4*)(ap + 8 * TT);
            pw0 = *(const float4*)(wp);
            pw1 = *(const float4*)(wp + (size_t)64 * DD);
        }

        // compute 16 k-steps from smem[buf]
#pragma unroll
        for (int kk = 0; kk < TK; ++kk) {
            const float4 a0 = *(const float4*)&As[buf][kk][ty * 8 + 0];
            const float4 a1 = *(const float4*)&As[buf][kk][ty * 8 + 4];
            const float4 b0 = *(const float4*)&Bs[buf][kk][tx * 8 + 0];
            const float4 b1 = *(const float4*)&Bs[buf][kk][tx * 8 + 4];

            ull rb2[4];
            PACK2(rb2[0], b0.x, b0.y);
            PACK2(rb2[1], b0.z, b0.w);
            PACK2(rb2[2], b1.x, b1.y);
            PACK2(rb2[3], b1.z, b1.w);

            ull ra2[8];
            PACK2(ra2[0], a0.x, a0.x);
            PACK2(ra2[1], a0.y, a0.y);
            PACK2(ra2[2], a0.z, a0.z);
            PACK2(ra2[3], a0.w, a0.w);
            PACK2(ra2[4], a1.x, a1.x);
            PACK2(ra2[5], a1.y, a1.y);
            PACK2(ra2[6], a1.z, a1.z);
            PACK2(ra2[7], a1.w, a1.w);

#pragma unroll
            for (int i = 0; i < 8; ++i)
#pragma unroll
                for (int j = 0; j < 4; ++j)
                    FMA2(blk2[i][j], ra2[i], rb2[j]);
        }

        // chunk boundary every 64 k (= every 4 tiles): plain fp32 add per lane
        if ((tile & 3) == 3) {
#pragma unroll
            for (int i = 0; i < 8; ++i)
#pragma unroll
                for (int j = 0; j < 4; ++j) {
                    ADD2(acc2[i][j], acc2[i][j], blk2[i][j]);
                    blk2[i][j] = zero2;
                }
        }

        buf ^= 1;
    }

    // epilogue: unpack, add bias (separately rounded), store
#pragma unroll
    for (int i = 0; i < 8; ++i) {
        const int m = m0 + ty * 8 + i;
        const int n = n0 + tx * 8;
        float v[8];
#pragma unroll
        for (int j = 0; j < 4; ++j) {
            UNPACK2(v[2 * j], v[2 * j + 1], acc2[i][j]);
        }
        float4 o0, o1;
        o0.x = __fadd_rn(v[0], bias[n + 0]);
        o0.y = __fadd_rn(v[1], bias[n + 1]);
        o0.z = __fadd_rn(v[2], bias[n + 2]);
        o0.w = __fadd_rn(v[3], bias[n + 3]);
        o1.x = __fadd_rn(v[4], bias[n + 4]);
        o1.y = __fadd_rn(v[5], bias[n + 5]);
        o1.z = __fadd_rn(v[6], bias[n + 6]);
        o1.w = __fadd_rn(v[7], bias[n + 7]);
        *(float4*)&g_psp[(size_t)m * NN + n]     = o0;
        *(float4*)&g_psp[(size_t)m * NN + n + 4] = o1;
    }
}

// ---------------------------------------------------------------------------
// LIF hard-reset scan over T (unchanged from passing R9 kernel).
// ---------------------------------------------------------------------------
__global__ __launch_bounds__(256) void k_scan(const float* __restrict__ decay,
                                              float* __restrict__ out,
                                              int write_vfinal) {
    const int idx = blockIdx.x * blockDim.x + threadIdx.x;  // b*N + n
    const int b = idx / NN;
    const int n = idx - b * NN;

    const float dec = decay[n];
    float v = 0.0f, s = 0.0f;
    float sp[TT];

    const float* p = g_psp + (size_t)b * TT * NN + n;
#pragma unroll
    for (int t = 0; t < TT; ++t) {
        float a = __fsub_rn(1.0f, s);
        float c = __fmul_rn(a, v);
        float d = __fmul_rn(c, dec);
        v = __fadd_rn(d, p[(size_t)t * NN]);
        s = (v > 0.5f) ? 1.0f : 0.0f;
        sp[t] = s;
    }

    float* o = out + (size_t)idx * TT;
#pragma unroll
    for (int t = 0; t < TT; t += 4) {
        *(float4*)&o[t] = make_float4(sp[t], sp[t + 1], sp[t + 2], sp[t + 3]);
    }
    if (write_vfinal) {
        out[(size_t)BB * NN * TT + idx] = v;
    }
}

// ---------------------------------------------------------------------------
extern "C" void kernel_launch(void* const* d_in, const int* in_sizes, int n_in,
                              void* d_out, int out_size) {
    const float* input = (const float*)d_in[0];  // [B, D, T]
    const float* W     = (const float*)d_in[1];  // [N, D]
    const float* bias  = (const float*)d_in[2];  // [N]
    const float* decay = (const float*)d_in[3];  // [N]
    float* out = (float*)d_out;

    const int write_vfinal =
        (out_size >= (int)((size_t)BB * NN * TT + (size_t)BB * NN)) ? 1 : 0;

    {
        dim3 grid(NN / TN, MM / TM);   // 16 x 64
        k_gemm<<<grid, 256>>>(input, W, bias);
    }
    {
        const int total = BB * NN;
        k_scan<<<total / 256, 256>>>(decay, out, write_vfinal);
    }
}

// round 16
// speedup vs baseline: 2.1328x; 1.0362x over previous
#include <cuda_runtime.h>
#include <cuda_bf16.h>
#include <cstdint>

// Problem constants
#define BB 128
#define DD 2048
#define NN 2048
#define TT 64
#define MM (BB * TT)   // 8192 rows of the GEMM

// FROZEN NUMERICS (validated R9/R12, rel_err 6.355139e-4):
//   psp[m,n] = fold over 64-wide k-chunks (plain fp32 add per boundary),
//   ascending-k fp32 FMA chain within each chunk, bias added last, then
//   op-by-op rounded LIF scan. f32x2 packed ops are bit-identical per lane.
//   Any change to this per-output op order is a correctness regression.

typedef unsigned long long ull;

// ---- packed fp32x2 helpers (Blackwell; lane-wise IEEE fp32 rn) ----
#define FMA2(d, a, b) \
    asm("fma.rn.f32x2 %0, %1, %2, %0;" : "+l"(d) : "l"(a), "l"(b))
#define ADD2(d, a, b) \
    asm("add.rn.f32x2 %0, %1, %2;" : "=l"(d) : "l"(a), "l"(b))
#define PACK2(d, lo, hi) \
    asm("mov.b64 %0, {%1, %2};" : "=l"(d) : "r"(__float_as_uint(lo)), "r"(__float_as_uint(hi)))
#define UNPACK2(lo, hi, s) \
    do { unsigned int _ulo, _uhi; \
         asm("mov.b64 {%0, %1}, %2;" : "=r"(_ulo), "=r"(_uhi) : "l"(s)); \
         lo = __uint_as_float(_ulo); hi = __uint_as_float(_uhi); } while (0)

// ---------------------------------------------------------------------------
// Fused GEMM + LIF scan.
//   psp[m,n] = chunked_sum_k X[m,k]*W[n,k] + bias[n],  X[m,k] = in[b,k,t],
//   m = b*64 + t. CTA tile 128(m) x 128(n) => each CTA owns ALL 64 timesteps
//   of 2 batches x 128 neurons, so the sequential scan fuses in the epilogue:
//   psp staged in smem (reusing the dead As/Bs arena), 256 threads remap to
//   256 (b,n) scan tasks, spikes written straight to d_out. No psp in DRAM.
// Mainloop: TK=16, 256 threads, 8m x 8n micro-tile, n-paired f32x2
// accumulators, double-buffered smem, 1 sync per tile.
// ---------------------------------------------------------------------------
#define TM 128
#define TN 128
#define TK 16
#define LDAB 132   // smem row pitch for As/Bs (floats), 16B-aligned
#define LDP  132   // psp stage pitch: MULTIPLE OF 4 (float4-aligned stores).
                   // Scan reads are consecutive-nloc per warp -> conflict-free
                   // for any pitch. (129 caused the R13 misaligned-address.)

#define AB_FLOATS (2 * TK * LDAB)          // 4224 floats per operand
#define PS_FLOATS (TM * LDP)               // 16896 floats
// arena = max(As+Bs, Ps) = max(8448, 16896) floats
#define ARENA_BYTES (PS_FLOATS * 4)        // 67584 B

__global__ __launch_bounds__(256) void k_gemm_fused(const float* __restrict__ in,
                                                    const float* __restrict__ W,
                                                    const float* __restrict__ bias,
                                                    const float* __restrict__ decay,
                                                    float* __restrict__ out,
                                                    int write_vfinal) {
    extern __shared__ float smem[];
    float* As = smem;                 // [2][TK][LDAB]
    float* Bs = smem + AB_FLOATS;     // [2][TK][LDAB]

    const int tid = threadIdx.x;
    const int m0  = blockIdx.y * TM;
    const int n0  = blockIdx.x * TN;

    // ---- A loader: slots tid and tid+256 over 16k x 32 (m/4) grid ----
    const int kkA  = tid >> 5;             // 0..7  (slot1: kk+8)
    const int lm4  = (tid & 31) * 4;       // 0..124
    const int bA   = (m0 + lm4) >> 6;      // batch
    const int tA   = (m0 + lm4) & 63;      // time
    const float* aptr = in + ((size_t)bA * DD + kkA) * TT + tA;

    // ---- B loader: slots tid and tid+256 over 128(n) x 4 (k/4) grid ----
    const int lnB  = tid >> 2;             // 0..63 (slot1: +64)
    const int kc4  = (tid & 3) * 4;        // 0,4,8,12
    const float* wptr = W + (size_t)(n0 + lnB) * DD + kc4;

    // ---- compute map: 16x16 threads, 8m x 8n (4 f32x2 n-pairs) ----
    const int tx = tid & 15;
    const int ty = tid >> 4;

    ull acc2[8][4], blk2[8][4];
    const ull zero2 = 0ull;
#pragma unroll
    for (int i = 0; i < 8; ++i)
#pragma unroll
        for (int j = 0; j < 4; ++j) { acc2[i][j] = zero2; blk2[i][j] = zero2; }

    // prologue: prefetch tile 0
    float4 pa0 = *(const float4*)(aptr);
    float4 pa1 = *(const float4*)(aptr + 8 * TT);
    float4 pw0 = *(const float4*)(wptr);
    float4 pw1 = *(const float4*)(wptr + (size_t)64 * DD);

    const int NTILES = DD / TK;  // 128
    int buf = 0;

    for (int tile = 0; tile < NTILES; ++tile) {
        float* Ab = As + buf * (TK * LDAB);
        float* Bb = Bs + buf * (TK * LDAB);

        *(float4*)&Ab[kkA * LDAB + lm4]       = pa0;
        *(float4*)&Ab[(kkA + 8) * LDAB + lm4] = pa1;
        Bb[(kc4 + 0) * LDAB + lnB] = pw0.x;
        Bb[(kc4 + 1) * LDAB + lnB] = pw0.y;
        Bb[(kc4 + 2) * LDAB + lnB] = pw0.z;
        Bb[(kc4 + 3) * LDAB + lnB] = pw0.w;
        Bb[(kc4 + 0) * LDAB + lnB + 64] = pw1.x;
        Bb[(kc4 + 1) * LDAB + lnB + 64] = pw1.y;
        Bb[(kc4 + 2) * LDAB + lnB + 64] = pw1.z;
        Bb[(kc4 + 3) * LDAB + lnB + 64] = pw1.w;
        __syncthreads();

        if (tile + 1 < NTILES) {
            const float* ap = aptr + (size_t)(tile + 1) * TK * TT;
            const float* wp = wptr + (size_t)(tile + 1) * TK;
            pa0 = *(const float4*)(ap);
            pa1 = *(const float4*)(ap + 8 * TT);
            pw0 = *(const float4*)(wp);
            pw1 = *(const float4*)(wp + (size_t)64 * DD);
        }

#pragma unroll
        for (int kk = 0; kk < TK; ++kk) {
            const float4 a0 = *(const float4*)&Ab[kk * LDAB + ty * 8 + 0];
            const float4 a1 = *(const float4*)&Ab[kk * LDAB + ty * 8 + 4];
            // n-pairs are contiguous: load directly as 64-bit words (no MOVs)
            const ull* brow = (const ull*)&Bb[kk * LDAB + tx * 8];
            ull rb2[4];
            rb2[0] = brow[0];
            rb2[1] = brow[1];
            rb2[2] = brow[2];
            rb2[3] = brow[3];

            ull ra2[8];
            PACK2(ra2[0], a0.x, a0.x);
            PACK2(ra2[1], a0.y, a0.y);
            PACK2(ra2[2], a0.z, a0.z);
            PACK2(ra2[3], a0.w, a0.w);
            PACK2(ra2[4], a1.x, a1.x);
            PACK2(ra2[5], a1.y, a1.y);
            PACK2(ra2[6], a1.z, a1.z);
            PACK2(ra2[7], a1.w, a1.w);

#pragma unroll
            for (int i = 0; i < 8; ++i)
#pragma unroll
                for (int j = 0; j < 4; ++j)
                    FMA2(blk2[i][j], ra2[i], rb2[j]);
        }

        // chunk boundary every 64 k (= 4 tiles): plain fp32 add per lane
        if ((tile & 3) == 3) {
#pragma unroll
            for (int i = 0; i < 8; ++i)
#pragma unroll
                for (int j = 0; j < 4; ++j) {
                    ADD2(acc2[i][j], acc2[i][j], blk2[i][j]);
                    blk2[i][j] = zero2;
                }
        }

        buf ^= 1;
    }

    // ---- epilogue: stage psp (+bias) into smem, then fused LIF scan ----
    __syncthreads();                 // all warps done reading As/Bs
    float* Ps = smem;                // reuse arena: [TM][LDP]

#pragma unroll
    for (int i = 0; i < 8; ++i) {
        const int mloc = ty * 8 + i;
        const int n    = n0 + tx * 8;
        float v[8];
#pragma unroll
        for (int j = 0; j < 4; ++j) {
            UNPACK2(v[2 * j], v[2 * j + 1], acc2[i][j]);
        }
        float4 o0, o1;
        o0.x = __fadd_rn(v[0], bias[n + 0]);
        o0.y = __fadd_rn(v[1], bias[n + 1]);
        o0.z = __fadd_rn(v[2], bias[n + 2]);
        o0.w = __fadd_rn(v[3], bias[n + 3]);
        o1.x = __fadd_rn(v[4], bias[n + 4]);
        o1.y = __fadd_rn(v[5], bias[n + 5]);
        o1.z = __fadd_rn(v[6], bias[n + 6]);
        o1.w = __fadd_rn(v[7], bias[n + 7]);
        *(float4*)&Ps[mloc * LDP + tx * 8]     = o0;
        *(float4*)&Ps[mloc * LDP + tx * 8 + 4] = o1;
    }
    __syncthreads();

    // scan: thread i -> (b_loc = i>>7, n_loc = i&127); full T in smem column
    {
        const int bloc = tid >> 7;
        const int nloc = tid & 127;
        const int ng   = n0 + nloc;
        const int bg   = (m0 >> 6) + bloc;

        const float dec = decay[ng];
        float v = 0.0f, s = 0.0f;
        float sp[TT];

        const float* col = Ps + (size_t)(bloc * 64) * LDP + nloc;
#pragma unroll
        for (int t = 0; t < TT; ++t) {
            float a = __fsub_rn(1.0f, s);
            float c = __fmul_rn(a, v);
            float d = __fmul_rn(c, dec);
            v = __fadd_rn(d, col[(size_t)t * LDP]);
            s = (v > 0.5f) ? 1.0f : 0.0f;
            sp[t] = s;
        }

        float* o = out + ((size_t)bg * NN + ng) * TT;
#pragma unroll
        for (int t = 0; t < TT; t += 4) {
            *(float4*)&o[t] = make_float4(sp[t], sp[t + 1], sp[t + 2], sp[t + 3]);
        }
        if (write_vfinal) {
            out[(size_t)BB * NN * TT + (size_t)bg * NN + ng] = v;
        }
    }
}

// ---------------------------------------------------------------------------
extern "C" void kernel_launch(void* const* d_in, const int* in_sizes, int n_in,
                              void* d_out, int out_size) {
    const float* input = (const float*)d_in[0];  // [B, D, T]
    const float* W     = (const float*)d_in[1];  // [N, D]
    const float* bias  = (const float*)d_in[2];  // [N]
    const float* decay = (const float*)d_in[3];  // [N]
    float* out = (float*)d_out;

    const int write_vfinal =
        (out_size >= (int)((size_t)BB * NN * TT + (size_t)BB * NN)) ? 1 : 0;

    // Opt in to >48KB dynamic smem (attribute persists; call is idempotent,
    // executes immediately even during graph capture, and is not an alloc).
    cudaFuncSetAttribute(k_gemm_fused,
                         cudaFuncAttributeMaxDynamicSharedMemorySize,
                         ARENA_BYTES);

    dim3 grid(NN / TN, MM / TM);   // 16 x 64
    k_gemm_fused<<<grid, 256, ARENA_BYTES>>>(input, W, bias, decay, out,
                                             write_vfinal);
}